// round 16
// baseline (speedup 1.0000x reference)
#include <cuda_runtime.h>
#include <cuda_fp16.h>
#include <cstdint>

// ---------------- problem constants ----------------
#define BB   32
#define CCH  64
#define TT   12
#define T2   10
#define NN   883
#define NP   896            // padded vertex count
#define KP   2688           // 3*NP padded K
#define NKT  42             // K tiles of 64
#define HP_ELEMS  (BB*CCH*TT*NP)
#define BADJ_ELEMS ((size_t)NP*KP)
#define NTHREADS 512

__device__ __half g_Ah[HP_ELEMS];
__device__ __half g_Bh[BADJ_ELEMS];

__device__ __forceinline__ uint32_t smem_u32_of(const void* p) {
    uint32_t a;
    asm("{ .reg .u64 t; cvta.to.shared.u64 t, %1; cvt.u32.u64 %0, t; }" : "=r"(a) : "l"(p));
    return a;
}
__device__ __forceinline__ float sigmoidf(float x) {
    return __fdividef(1.f, 1.f + __expf(-x));
}
#define SW128(o) ((o) ^ (((o) >> 3) & 0x70))

// cp.async
__device__ __forceinline__ void cpa16(uint32_t dst, const void* src) {
    asm volatile("cp.async.cg.shared.global [%0], [%1], 16;" :: "r"(dst), "l"(src));
}
__device__ __forceinline__ void cpa_commit() { asm volatile("cp.async.commit_group;" ::: "memory"); }
template<int N> __device__ __forceinline__ void cpa_wait() {
    asm volatile("cp.async.wait_group %0;" :: "n"(N) : "memory");
}

// warp tensor ops (baseline PTX)
__device__ __forceinline__ void ldm4(uint32_t* r, uint32_t addr) {
    asm volatile("ldmatrix.sync.aligned.m8n8.x4.shared.b16 {%0,%1,%2,%3}, [%4];"
                 : "=r"(r[0]), "=r"(r[1]), "=r"(r[2]), "=r"(r[3]) : "r"(addr));
}
__device__ __forceinline__ void ldm4t(uint32_t* r, uint32_t addr) {
    asm volatile("ldmatrix.sync.aligned.m8n8.x4.trans.shared.b16 {%0,%1,%2,%3}, [%4];"
                 : "=r"(r[0]), "=r"(r[1]), "=r"(r[2]), "=r"(r[3]) : "r"(addr));
}
__device__ __forceinline__ void mma16816(float* d, const uint32_t* a, const uint32_t* b) {
    asm volatile("mma.sync.aligned.m16n8k16.row.col.f32.f16.f16.f32 "
                 "{%0,%1,%2,%3}, {%4,%5,%6,%7}, {%8,%9}, {%0,%1,%2,%3};"
                 : "+f"(d[0]), "+f"(d[1]), "+f"(d[2]), "+f"(d[3])
                 : "r"(a[0]), "r"(a[1]), "r"(a[2]), "r"(a[3]), "r"(b[0]), "r"(b[1]));
}

// ---------------------------------------------------------------------------
// fused prep kernel (256 threads) — R14 exact (best measured):
//   blocks [0, PH_BLOCKS)           : H -> fp16 padded, WARP-PER-ROW
//   blocks [PH_BLOCKS, +PB_BLOCKS)  : B -> fp16 padded, uint4-vectorized
// ---------------------------------------------------------------------------
#define PH_ROWS   (BB * CCH * TT)                 // 24576 rows, 1 warp each
#define PH_BLOCKS (PH_ROWS / 8)                   // 3072 blocks x 8 warps
#define PB_VEC    ((int)(BADJ_ELEMS / 8))         // 301056 uint4 stores
#define PB_BLOCKS ((PB_VEC + 255) / 256)          // 1176

__global__ void prep_fused(const float* __restrict__ x,
                           const float* __restrict__ te,
                           const float* __restrict__ se,
                           const float* __restrict__ adj) {
    const int tid = threadIdx.x;
    if (blockIdx.x < PH_BLOCKS) {
        int gw   = blockIdx.x * 8 + (tid >> 5);
        int lane = tid & 31;
        int t = gw % TT;
        int c = (gw / TT) % CCH;
        const float* xr = x + (size_t)gw * NN;
        const float* sr = se + (size_t)c * NN;
        float tv = __ldg(&te[c * TT + t]);
        __half* dst = g_Ah + (size_t)gw * NP;
#pragma unroll
        for (int i = 0; i < NP / 32; i++) {
            int n = i * 32 + lane;
            float v = (n < NN) ? (__ldg(&xr[n]) + tv + __ldg(&sr[n])) : 0.f;
            dst[n] = __float2half(v);
        }
    } else {
        int v = (blockIdx.x - PH_BLOCKS) * 256 + tid;
        if (v >= PB_VEC) return;
        size_t idx = (size_t)v * 8;
        int kc = (int)(idx % KP);
        int m  = (int)(idx / KP);
        int j  = kc / NP;
        int k0 = kc % NP;
        __half h[8];
        if (m < NN) {
            const float* ar = adj + (size_t)(NN + m) * (3 * NN) + j * NN;
#pragma unroll
            for (int q = 0; q < 8; q++) {
                int kk = k0 + q;
                h[q] = __float2half((kk < NN) ? __ldg(&ar[kk]) : 0.f);
            }
        } else {
#pragma unroll
            for (int q = 0; q < 8; q++) h[q] = __float2half(0.f);
        }
        *(uint4*)&g_Bh[idx] = *(const uint4*)h;
    }
}

// ---------------------------------------------------------------------------
// main kernel (512 threads, 16 warps) — converged config; ks-body reordered:
// B LDSMs issued first, MMAs consume earliest-issued frags first.
// GEMM: D[256,128] = A(fp16)[256,2688] x B(fp16)[2688,128]
//   warp tile 64m x 32n (4m x 4n warp grid); M covers 4 bt groups.
// SMEM: 4 stages x 48KB (A 32K | B 16K), SW128 rows of 64 fp16.
// ---------------------------------------------------------------------------
#define STAGE_BYTES 49152
#define DSMEM_BYTES (4 * STAGE_BYTES)   // 196608
#define GS_STRIDE 136                   // halfs; 272B rows
#define GS_BYTES  (256 * GS_STRIDE * 2) // 69632
#define WT_OFF GS_BYTES
#define WT_DSTR 72                      // halfs; 144B rows

__global__ __launch_bounds__(NTHREADS, 1)
void stsgcl_mma_kernel(const float* __restrict__ Wp,
                       const float* __restrict__ bias,
                       float* __restrict__ out) {
    extern __shared__ char dsm[];

    const int tid  = threadIdx.x;
    const int m0   = blockIdx.x * 128;
    const int bt0g = blockIdx.y * 4;

    const uint32_t smem = smem_u32_of(dsm);

    // ---- loader precompute: 6 x 16B chunks per stage (48KB / 512 thr) ----
    const char* src0[6];
    uint32_t    dsto[6];
#pragma unroll
    for (int i = 0; i < 6; i++) {
        int L = tid + NTHREADS * i;
        if (L < 2048) {                  // A: 256 rows x 8 chunks
            int r   = L >> 3;
            int c16 = L & 7;
            int g4  = r >> 6;
            int ch  = r & 63;
            int btg = bt0g + g4;
            int bb  = btg / T2;
            int tt  = btg % T2;
            size_t e = ((size_t)(bb * CCH + ch) * TT + tt) * NP + c16 * 8;
            src0[i] = (const char*)g_Ah + e * 2;
            dsto[i] = SW128(r * 128 + c16 * 16);
        } else {                         // B: 128 rows x 8 chunks
            int r    = (L >> 3) & 127;
            int c16  = L & 7;
            size_t e = (size_t)(m0 + r) * KP + c16 * 8;
            src0[i] = (const char*)g_Bh + e * 2;
            dsto[i] = 32768 + SW128(r * 128 + c16 * 16);
        }
    }

    // ---- prologue: fill stages 0,1,2 with tiles 0,1,2 ----
#pragma unroll
    for (int s = 0; s < 3; s++) {
        uint32_t sb = smem + s * STAGE_BYTES;
#pragma unroll
        for (int i = 0; i < 6; i++) cpa16(sb + dsto[i], src0[i] + (size_t)s * 128);
        cpa_commit();
    }

    // ---- MMA setup (warp 64m x 32n; wm = wid&3, wn = wid>>2) ----
    const int lane = tid & 31;
    const int wid  = tid >> 5;
    const int wm   = wid & 3;
    const int wn   = wid >> 2;
    const int rsel = lane & 7;
    const int tsel = lane >> 3;
    const int grp  = lane >> 2;
    const int thr  = lane & 3;

    const int aRowBase = wm * 64 + ((tsel & 1) << 3) + rsel;
    const uint32_t kbeA = (uint32_t)((tsel >> 1) << 4);
    const uint32_t aswz = (uint32_t)((aRowBase & 7) << 4);
    uint32_t aoff[4];
#pragma unroll
    for (int mf = 0; mf < 4; mf++) aoff[mf] = (uint32_t)((aRowBase + mf * 16) * 128);

    const int bRowBase = wn * 32 + ((tsel >> 1) << 3) + rsel;
    const uint32_t kbeB = (uint32_t)((tsel & 1) << 4);
    const uint32_t bswz = (uint32_t)((bRowBase & 7) << 4);
    uint32_t boff[2];
#pragma unroll
    for (int nf2 = 0; nf2 < 2; nf2++) boff[nf2] = (uint32_t)((bRowBase + nf2 * 16) * 128);

    float d[4][4][4];
#pragma unroll
    for (int i = 0; i < 4; i++)
#pragma unroll
        for (int j = 0; j < 4; j++)
#pragma unroll
            for (int q = 0; q < 4; q++) d[i][j][q] = 0.f;

    // ---- main K loop: one barrier per iteration ----
    for (int kt = 0; kt < NKT; kt++) {
        if (kt <= NKT - 3)      cpa_wait<2>();
        else if (kt == NKT - 2) cpa_wait<1>();
        else                    cpa_wait<0>();
        __syncthreads();

        if (kt <= NKT - 4) {
            const uint32_t rb = smem + ((kt + 3) & 3) * STAGE_BYTES;
            size_t koff = (size_t)(kt + 3) * 128;
#pragma unroll
            for (int i = 0; i < 6; i++) cpa16(rb + dsto[i], src0[i] + koff);
            cpa_commit();
        }

        const uint32_t sb = smem + (kt & 3) * STAGE_BYTES;
#pragma unroll
        for (int ks = 0; ks < 4; ks++) {
            const uint32_t kb = (uint32_t)(ks * 32);
            // B first: earliest-issued LDSMs feed the first MMA group
            uint32_t bh0[4], bh1[4];
            ldm4(bh0, sb + 32768 + boff[0] + ((kb + kbeB) ^ bswz));
            ldm4(bh1, sb + 32768 + boff[1] + ((kb + kbeB) ^ bswz));
            uint32_t a[4][4];
#pragma unroll
            for (int mf = 0; mf < 4; mf++)
                ldm4(a[mf], sb + aoff[mf] + ((kb + kbeA) ^ aswz));
            // MMAs B-major: group 0 (bh0) first, then group 1 (bh1)
#pragma unroll
            for (int mf = 0; mf < 4; mf++) {
                mma16816(d[mf][0], a[mf], bh0);
                mma16816(d[mf][1], a[mf], bh0 + 2);
            }
#pragma unroll
            for (int mf = 0; mf < 4; mf++) {
                mma16816(d[mf][2], a[mf], bh1);
                mma16816(d[mf][3], a[mf], bh1 + 2);
            }
        }
    }
    __syncthreads();   // all MMAs done before Gs overwrites stage smem

    // ---- stage G (fp16) to Gs[256][136] ----
    {
        __half* Gs = (__half*)dsm;
#pragma unroll
        for (int mf = 0; mf < 4; mf++)
#pragma unroll
            for (int nf = 0; nf < 4; nf++) {
                int row = wm * 64 + mf * 16 + grp;
                int col = wn * 32 + nf * 8 + thr * 2;
                *(__half2*)&Gs[row * GS_STRIDE + col] =
                    __floats2half2_rn(d[mf][nf][0], d[mf][nf][1]);
                *(__half2*)&Gs[(row + 8) * GS_STRIDE + col] =
                    __floats2half2_rn(d[mf][nf][2], d[mf][nf][3]);
            }
    }

    // ---- stage W^T (fp16): Wt[g][sel][d][72], sel 0=lin 1=gate ----
    {
        __half* Wt = (__half*)(dsm + WT_OFF);
#pragma unroll
        for (int it = 0; it < 12; it++) {
            int lin = (tid + NTHREADS * it) * 4;   // over 3*64*128 = 24576
            int g   = lin >> 13;
            int c   = (lin >> 7) & 63;
            int dd  = lin & 127;
            float4 w = *(const float4*)&Wp[((size_t)(g * CCH + c)) * 128 + dd];
            int gsel = g * 2 + (dd >> 6);
            int d0   = dd & 63;
            __half* base = Wt + (size_t)gsel * 64 * WT_DSTR + c;
            base[(d0 + 0) * WT_DSTR] = __float2half(w.x);
            base[(d0 + 1) * WT_DSTR] = __float2half(w.y);
            base[(d0 + 2) * WT_DSTR] = __float2half(w.z);
            base[(d0 + 3) * WT_DSTR] = __float2half(w.w);
        }
    }
    __syncthreads();

    // ---- tensor GLU epilogue: Z[64d,128m] per (bt, g) ----
    const int bq = wid >> 3;
    const int dw = wid & 1;
    const int mw = (wid >> 1) & 3;
    const uint32_t GsB = smem;
    const uint32_t WtB = smem + WT_OFF;

    const int aRow2 = dw * 32 + ((tsel & 1) << 3) + rsel;
    const uint32_t akOff = (uint32_t)(((tsel >> 1) << 3) * 2);
    const int bkRow = ((tsel & 1) << 3) + rsel;
    const int bmOff = mw * 32 + ((tsel >> 1) << 3);

    for (int it = 0; it < 2; it++) {
        const int bsel = bq * 2 + it;
        float omax[2][4][4];
#pragma unroll
        for (int mf = 0; mf < 2; mf++)
#pragma unroll
            for (int nf = 0; nf < 4; nf++)
#pragma unroll
                for (int q = 0; q < 4; q++) omax[mf][nf][q] = -3.4e38f;

        for (int g = 0; g < 3; g++) {
            float zl[2][4][4], zg[2][4][4];
#pragma unroll
            for (int mf = 0; mf < 2; mf++) {
                int dbase = dw * 32 + mf * 16 + grp;
                float bl0 = __ldg(&bias[g * 128 + dbase]);
                float bl8 = __ldg(&bias[g * 128 + dbase + 8]);
                float bg0 = __ldg(&bias[g * 128 + 64 + dbase]);
                float bg8 = __ldg(&bias[g * 128 + 64 + dbase + 8]);
#pragma unroll
                for (int nf = 0; nf < 4; nf++) {
                    zl[mf][nf][0] = bl0; zl[mf][nf][1] = bl0;
                    zl[mf][nf][2] = bl8; zl[mf][nf][3] = bl8;
                    zg[mf][nf][0] = bg0; zg[mf][nf][1] = bg0;
                    zg[mf][nf][2] = bg8; zg[mf][nf][3] = bg8;
                }
            }

            const uint32_t WL = WtB + (uint32_t)(g * 2) * 64 * WT_DSTR * 2;
#pragma unroll
            for (int ks = 0; ks < 4; ks++) {
                uint32_t al[2][4], ag[2][4];
#pragma unroll
                for (int mf = 0; mf < 2; mf++) {
                    uint32_t addr = WL + (uint32_t)(aRow2 + mf * 16) * (WT_DSTR * 2)
                                       + akOff + (uint32_t)(ks * 16 * 2);
                    ldm4(al[mf], addr);
                    ldm4(ag[mf], addr + 64 * WT_DSTR * 2);
                }
                uint32_t bb[4][2];
#pragma unroll
                for (int mt = 0; mt < 2; mt++) {
                    uint32_t addr = GsB
                        + (uint32_t)(bsel * 64 + ks * 16 + bkRow) * (GS_STRIDE * 2)
                        + (uint32_t)(bmOff + mt * 16) * 2;
                    uint32_t tmp[4];
                    ldm4t(tmp, addr);
                    bb[2 * mt][0] = tmp[0]; bb[2 * mt][1] = tmp[1];
                    bb[2 * mt + 1][0] = tmp[2]; bb[2 * mt + 1][1] = tmp[3];
                }
#pragma unroll
                for (int mf = 0; mf < 2; mf++)
#pragma unroll
                    for (int nf = 0; nf < 4; nf++) {
                        mma16816(zl[mf][nf], al[mf], bb[nf]);
                        mma16816(zg[mf][nf], ag[mf], bb[nf]);
                    }
            }

#pragma unroll
            for (int mf = 0; mf < 2; mf++)
#pragma unroll
                for (int nf = 0; nf < 4; nf++)
#pragma unroll
                    for (int q = 0; q < 4; q++) {
                        float v = zl[mf][nf][q] * sigmoidf(zg[mf][nf][q]);
                        omax[mf][nf][q] = fmaxf(omax[mf][nf][q], v);
                    }
        }

        // store out[b, d, t, m]  (scalar stores: NN odd stride)
        const int btg = bt0g + bsel;
        const int bb2 = btg / T2;
        const int tb  = btg % T2;
#pragma unroll
        for (int mf = 0; mf < 2; mf++) {
#pragma unroll
            for (int q2 = 0; q2 < 2; q2++) {
                int dd = dw * 32 + mf * 16 + grp + q2 * 8;
                size_t obase = ((size_t)(bb2 * CCH + dd) * T2 + tb) * NN;
#pragma unroll
                for (int nf = 0; nf < 4; nf++) {
                    int m = m0 + mw * 32 + nf * 8 + thr * 2;
                    if (m < NN)     out[obase + m]     = omax[mf][nf][q2 * 2];
                    if (m + 1 < NN) out[obase + m + 1] = omax[mf][nf][q2 * 2 + 1];
                }
            }
        }
    }
}

// ---------------------------------------------------------------------------
extern "C" void kernel_launch(void* const* d_in, const int* in_sizes, int n_in,
                              void* d_out, int out_size) {
    const float* x    = (const float*)d_in[0];
    const float* te   = (const float*)d_in[1];
    const float* se   = (const float*)d_in[2];
    const float* adj  = (const float*)d_in[3];
    const float* Wp   = (const float*)d_in[4];
    const float* bias = (const float*)d_in[5];
    float* out = (float*)d_out;

    cudaFuncSetAttribute(stsgcl_mma_kernel,
                         cudaFuncAttributeMaxDynamicSharedMemorySize, DSMEM_BYTES);

    prep_fused<<<PH_BLOCKS + PB_BLOCKS, 256>>>(x, te, se, adj);

    dim3 grid(NP / 128, 80);   // (7, 80): m-tiles x bt-quads
    stsgcl_mma_kernel<<<grid, NTHREADS, DSMEM_BYTES>>>(Wp, bias, out);
}

// round 17
// speedup vs baseline: 1.0161x; 1.0161x over previous
#include <cuda_runtime.h>
#include <cuda_fp16.h>
#include <cstdint>

// ---------------- problem constants ----------------
#define BB   32
#define CCH  64
#define TT   12
#define T2   10
#define NN   883
#define NP   896            // padded vertex count
#define KP   2688           // 3*NP padded K
#define NKT  42             // K tiles of 64
#define HP_ELEMS  (BB*CCH*TT*NP)
#define BADJ_ELEMS ((size_t)NP*KP)
#define NTHREADS 512

__device__ __half g_Ah[HP_ELEMS];
__device__ __half g_Bh[BADJ_ELEMS];

__device__ __forceinline__ uint32_t smem_u32_of(const void* p) {
    uint32_t a;
    asm("{ .reg .u64 t; cvta.to.shared.u64 t, %1; cvt.u32.u64 %0, t; }" : "=r"(a) : "l"(p));
    return a;
}
__device__ __forceinline__ float sigmoidf(float x) {
    return __fdividef(1.f, 1.f + __expf(-x));
}
#define SW128(o) ((o) ^ (((o) >> 3) & 0x70))

// cp.async
__device__ __forceinline__ void cpa16(uint32_t dst, const void* src) {
    asm volatile("cp.async.cg.shared.global [%0], [%1], 16;" :: "r"(dst), "l"(src));
}
__device__ __forceinline__ void cpa_commit() { asm volatile("cp.async.commit_group;" ::: "memory"); }
template<int N> __device__ __forceinline__ void cpa_wait() {
    asm volatile("cp.async.wait_group %0;" :: "n"(N) : "memory");
}

// warp tensor ops (baseline PTX)
__device__ __forceinline__ void ldm4(uint32_t* r, uint32_t addr) {
    asm volatile("ldmatrix.sync.aligned.m8n8.x4.shared.b16 {%0,%1,%2,%3}, [%4];"
                 : "=r"(r[0]), "=r"(r[1]), "=r"(r[2]), "=r"(r[3]) : "r"(addr));
}
__device__ __forceinline__ void ldm4t(uint32_t* r, uint32_t addr) {
    asm volatile("ldmatrix.sync.aligned.m8n8.x4.trans.shared.b16 {%0,%1,%2,%3}, [%4];"
                 : "=r"(r[0]), "=r"(r[1]), "=r"(r[2]), "=r"(r[3]) : "r"(addr));
}
__device__ __forceinline__ void mma16816(float* d, const uint32_t* a, const uint32_t* b) {
    asm volatile("mma.sync.aligned.m16n8k16.row.col.f32.f16.f16.f32 "
                 "{%0,%1,%2,%3}, {%4,%5,%6,%7}, {%8,%9}, {%0,%1,%2,%3};"
                 : "+f"(d[0]), "+f"(d[1]), "+f"(d[2]), "+f"(d[3])
                 : "r"(a[0]), "r"(a[1]), "r"(a[2]), "r"(a[3]), "r"(b[0]), "r"(b[1]));
}

// ---------------------------------------------------------------------------
// fused prep kernel (256 threads) — R14 exact (best measured):
//   blocks [0, PH_BLOCKS)           : H -> fp16 padded, WARP-PER-ROW
//   blocks [PH_BLOCKS, +PB_BLOCKS)  : B -> fp16 padded, uint4-vectorized
// ---------------------------------------------------------------------------
#define PH_ROWS   (BB * CCH * TT)                 // 24576 rows, 1 warp each
#define PH_BLOCKS (PH_ROWS / 8)                   // 3072 blocks x 8 warps
#define PB_VEC    ((int)(BADJ_ELEMS / 8))         // 301056 uint4 stores
#define PB_BLOCKS ((PB_VEC + 255) / 256)          // 1176

__global__ void prep_fused(const float* __restrict__ x,
                           const float* __restrict__ te,
                           const float* __restrict__ se,
                           const float* __restrict__ adj) {
    const int tid = threadIdx.x;
    if (blockIdx.x < PH_BLOCKS) {
        int gw   = blockIdx.x * 8 + (tid >> 5);
        int lane = tid & 31;
        int t = gw % TT;
        int c = (gw / TT) % CCH;
        const float* xr = x + (size_t)gw * NN;
        const float* sr = se + (size_t)c * NN;
        float tv = __ldg(&te[c * TT + t]);
        __half* dst = g_Ah + (size_t)gw * NP;
#pragma unroll
        for (int i = 0; i < NP / 32; i++) {
            int n = i * 32 + lane;
            float v = (n < NN) ? (__ldg(&xr[n]) + tv + __ldg(&sr[n])) : 0.f;
            dst[n] = __float2half(v);
        }
    } else {
        int v = (blockIdx.x - PH_BLOCKS) * 256 + tid;
        if (v >= PB_VEC) return;
        size_t idx = (size_t)v * 8;
        int kc = (int)(idx % KP);
        int m  = (int)(idx / KP);
        int j  = kc / NP;
        int k0 = kc % NP;
        __half h[8];
        if (m < NN) {
            const float* ar = adj + (size_t)(NN + m) * (3 * NN) + j * NN;
#pragma unroll
            for (int q = 0; q < 8; q++) {
                int kk = k0 + q;
                h[q] = __float2half((kk < NN) ? __ldg(&ar[kk]) : 0.f);
            }
        } else {
#pragma unroll
            for (int q = 0; q < 8; q++) h[q] = __float2half(0.f);
        }
        *(uint4*)&g_Bh[idx] = *(const uint4*)h;
    }
}

// ---------------------------------------------------------------------------
// main kernel (512 threads, 16 warps) — converged best config (R9/R13/R14).
// GEMM: D[256,128] = A(fp16)[256,2688] x B(fp16)[2688,128]
//   warp tile 64m x 32n (4m x 4n warp grid); M covers 4 bt groups.
// SMEM: 4 stages x 48KB (A 32K | B 16K), SW128 rows of 64 fp16.
// Single-sync pipeline; tensor GLU epilogue, warp-halves split bsel pairs.
// ---------------------------------------------------------------------------
#define STAGE_BYTES 49152
#define DSMEM_BYTES (4 * STAGE_BYTES)   // 196608
#define GS_STRIDE 136                   // halfs; 272B rows
#define GS_BYTES  (256 * GS_STRIDE * 2) // 69632
#define WT_OFF GS_BYTES
#define WT_DSTR 72                      // halfs; 144B rows

__global__ __launch_bounds__(NTHREADS, 1)
void stsgcl_mma_kernel(const float* __restrict__ Wp,
                       const float* __restrict__ bias,
                       float* __restrict__ out) {
    extern __shared__ char dsm[];

    const int tid  = threadIdx.x;
    const int m0   = blockIdx.x * 128;
    const int bt0g = blockIdx.y * 4;

    const uint32_t smem = smem_u32_of(dsm);

    // ---- loader precompute: 6 x 16B chunks per stage (48KB / 512 thr) ----
    const char* src0[6];
    uint32_t    dsto[6];
#pragma unroll
    for (int i = 0; i < 6; i++) {
        int L = tid + NTHREADS * i;
        if (L < 2048) {                  // A: 256 rows x 8 chunks
            int r   = L >> 3;
            int c16 = L & 7;
            int g4  = r >> 6;
            int ch  = r & 63;
            int btg = bt0g + g4;
            int bb  = btg / T2;
            int tt  = btg % T2;
            size_t e = ((size_t)(bb * CCH + ch) * TT + tt) * NP + c16 * 8;
            src0[i] = (const char*)g_Ah + e * 2;
            dsto[i] = SW128(r * 128 + c16 * 16);
        } else {                         // B: 128 rows x 8 chunks
            int r    = (L >> 3) & 127;
            int c16  = L & 7;
            size_t e = (size_t)(m0 + r) * KP + c16 * 8;
            src0[i] = (const char*)g_Bh + e * 2;
            dsto[i] = 32768 + SW128(r * 128 + c16 * 16);
        }
    }

    // ---- prologue: fill stages 0,1,2 with tiles 0,1,2 ----
#pragma unroll
    for (int s = 0; s < 3; s++) {
        uint32_t sb = smem + s * STAGE_BYTES;
#pragma unroll
        for (int i = 0; i < 6; i++) cpa16(sb + dsto[i], src0[i] + (size_t)s * 128);
        cpa_commit();
    }

    // ---- MMA setup (warp 64m x 32n; wm = wid&3, wn = wid>>2) ----
    const int lane = tid & 31;
    const int wid  = tid >> 5;
    const int wm   = wid & 3;
    const int wn   = wid >> 2;
    const int rsel = lane & 7;
    const int tsel = lane >> 3;
    const int grp  = lane >> 2;
    const int thr  = lane & 3;

    const int aRowBase = wm * 64 + ((tsel & 1) << 3) + rsel;
    const uint32_t kbeA = (uint32_t)((tsel >> 1) << 4);
    const uint32_t aswz = (uint32_t)((aRowBase & 7) << 4);
    uint32_t aoff[4];
#pragma unroll
    for (int mf = 0; mf < 4; mf++) aoff[mf] = (uint32_t)((aRowBase + mf * 16) * 128);

    const int bRowBase = wn * 32 + ((tsel >> 1) << 3) + rsel;
    const uint32_t kbeB = (uint32_t)((tsel & 1) << 4);
    const uint32_t bswz = (uint32_t)((bRowBase & 7) << 4);
    uint32_t boff[2];
#pragma unroll
    for (int nf2 = 0; nf2 < 2; nf2++) boff[nf2] = (uint32_t)((bRowBase + nf2 * 16) * 128);

    float d[4][4][4];
#pragma unroll
    for (int i = 0; i < 4; i++)
#pragma unroll
        for (int j = 0; j < 4; j++)
#pragma unroll
            for (int q = 0; q < 4; q++) d[i][j][q] = 0.f;

    // ---- main K loop: one barrier per iteration ----
    for (int kt = 0; kt < NKT; kt++) {
        if (kt <= NKT - 3)      cpa_wait<2>();
        else if (kt == NKT - 2) cpa_wait<1>();
        else                    cpa_wait<0>();
        __syncthreads();

        if (kt <= NKT - 4) {
            const uint32_t rb = smem + ((kt + 3) & 3) * STAGE_BYTES;
            size_t koff = (size_t)(kt + 3) * 128;
#pragma unroll
            for (int i = 0; i < 6; i++) cpa16(rb + dsto[i], src0[i] + koff);
            cpa_commit();
        }

        const uint32_t sb = smem + (kt & 3) * STAGE_BYTES;
#pragma unroll
        for (int ks = 0; ks < 4; ks++) {
            const uint32_t kb = (uint32_t)(ks * 32);
            uint32_t a[4][4];
#pragma unroll
            for (int mf = 0; mf < 4; mf++)
                ldm4(a[mf], sb + aoff[mf] + ((kb + kbeA) ^ aswz));
#pragma unroll
            for (int nf2 = 0; nf2 < 2; nf2++) {
                uint32_t bh[4];
                ldm4(bh, sb + 32768 + boff[nf2] + ((kb + kbeB) ^ bswz));
#pragma unroll
                for (int mf = 0; mf < 4; mf++) {
                    mma16816(d[mf][2 * nf2],     a[mf], bh);
                    mma16816(d[mf][2 * nf2 + 1], a[mf], bh + 2);
                }
            }
        }
    }
    __syncthreads();   // all MMAs done before Gs overwrites stage smem

    // ---- stage G (fp16) to Gs[256][136] ----
    {
        __half* Gs = (__half*)dsm;
#pragma unroll
        for (int mf = 0; mf < 4; mf++)
#pragma unroll
            for (int nf = 0; nf < 4; nf++) {
                int row = wm * 64 + mf * 16 + grp;
                int col = wn * 32 + nf * 8 + thr * 2;
                *(__half2*)&Gs[row * GS_STRIDE + col] =
                    __floats2half2_rn(d[mf][nf][0], d[mf][nf][1]);
                *(__half2*)&Gs[(row + 8) * GS_STRIDE + col] =
                    __floats2half2_rn(d[mf][nf][2], d[mf][nf][3]);
            }
    }

    // ---- stage W^T (fp16): Wt[g][sel][d][72], sel 0=lin 1=gate ----
    {
        __half* Wt = (__half*)(dsm + WT_OFF);
#pragma unroll
        for (int it = 0; it < 12; it++) {
            int lin = (tid + NTHREADS * it) * 4;   // over 3*64*128 = 24576
            int g   = lin >> 13;
            int c   = (lin >> 7) & 63;
            int dd  = lin & 127;
            float4 w = *(const float4*)&Wp[((size_t)(g * CCH + c)) * 128 + dd];
            int gsel = g * 2 + (dd >> 6);
            int d0   = dd & 63;
            __half* base = Wt + (size_t)gsel * 64 * WT_DSTR + c;
            base[(d0 + 0) * WT_DSTR] = __float2half(w.x);
            base[(d0 + 1) * WT_DSTR] = __float2half(w.y);
            base[(d0 + 2) * WT_DSTR] = __float2half(w.z);
            base[(d0 + 3) * WT_DSTR] = __float2half(w.w);
        }
    }
    __syncthreads();

    // ---- tensor GLU epilogue: Z[64d,128m] per (bt, g) ----
    const int bq = wid >> 3;
    const int dw = wid & 1;
    const int mw = (wid >> 1) & 3;
    const uint32_t GsB = smem;
    const uint32_t WtB = smem + WT_OFF;

    const int aRow2 = dw * 32 + ((tsel & 1) << 3) + rsel;
    const uint32_t akOff = (uint32_t)(((tsel >> 1) << 3) * 2);
    const int bkRow = ((tsel & 1) << 3) + rsel;
    const int bmOff = mw * 32 + ((tsel >> 1) << 3);

    for (int it = 0; it < 2; it++) {
        const int bsel = bq * 2 + it;
        float omax[2][4][4];
#pragma unroll
        for (int mf = 0; mf < 2; mf++)
#pragma unroll
            for (int nf = 0; nf < 4; nf++)
#pragma unroll
                for (int q = 0; q < 4; q++) omax[mf][nf][q] = -3.4e38f;

        for (int g = 0; g < 3; g++) {
            float zl[2][4][4], zg[2][4][4];
#pragma unroll
            for (int mf = 0; mf < 2; mf++) {
                int dbase = dw * 32 + mf * 16 + grp;
                float bl0 = __ldg(&bias[g * 128 + dbase]);
                float bl8 = __ldg(&bias[g * 128 + dbase + 8]);
                float bg0 = __ldg(&bias[g * 128 + 64 + dbase]);
                float bg8 = __ldg(&bias[g * 128 + 64 + dbase + 8]);
#pragma unroll
                for (int nf = 0; nf < 4; nf++) {
                    zl[mf][nf][0] = bl0; zl[mf][nf][1] = bl0;
                    zl[mf][nf][2] = bl8; zl[mf][nf][3] = bl8;
                    zg[mf][nf][0] = bg0; zg[mf][nf][1] = bg0;
                    zg[mf][nf][2] = bg8; zg[mf][nf][3] = bg8;
                }
            }

            const uint32_t WL = WtB + (uint32_t)(g * 2) * 64 * WT_DSTR * 2;
#pragma unroll
            for (int ks = 0; ks < 4; ks++) {
                uint32_t al[2][4], ag[2][4];
#pragma unroll
                for (int mf = 0; mf < 2; mf++) {
                    uint32_t addr = WL + (uint32_t)(aRow2 + mf * 16) * (WT_DSTR * 2)
                                       + akOff + (uint32_t)(ks * 16 * 2);
                    ldm4(al[mf], addr);
                    ldm4(ag[mf], addr + 64 * WT_DSTR * 2);
                }
                uint32_t bb[4][2];
#pragma unroll
                for (int mt = 0; mt < 2; mt++) {
                    uint32_t addr = GsB
                        + (uint32_t)(bsel * 64 + ks * 16 + bkRow) * (GS_STRIDE * 2)
                        + (uint32_t)(bmOff + mt * 16) * 2;
                    uint32_t tmp[4];
                    ldm4t(tmp, addr);
                    bb[2 * mt][0] = tmp[0]; bb[2 * mt][1] = tmp[1];
                    bb[2 * mt + 1][0] = tmp[2]; bb[2 * mt + 1][1] = tmp[3];
                }
#pragma unroll
                for (int mf = 0; mf < 2; mf++)
#pragma unroll
                    for (int nf = 0; nf < 4; nf++) {
                        mma16816(zl[mf][nf], al[mf], bb[nf]);
                        mma16816(zg[mf][nf], ag[mf], bb[nf]);
                    }
            }

#pragma unroll
            for (int mf = 0; mf < 2; mf++)
#pragma unroll
                for (int nf = 0; nf < 4; nf++)
#pragma unroll
                    for (int q = 0; q < 4; q++) {
                        float v = zl[mf][nf][q] * sigmoidf(zg[mf][nf][q]);
                        omax[mf][nf][q] = fmaxf(omax[mf][nf][q], v);
                    }
        }

        // store out[b, d, t, m]  (scalar stores: NN odd stride)
        const int btg = bt0g + bsel;
        const int bb2 = btg / T2;
        const int tb  = btg % T2;
#pragma unroll
        for (int mf = 0; mf < 2; mf++) {
#pragma unroll
            for (int q2 = 0; q2 < 2; q2++) {
                int dd = dw * 32 + mf * 16 + grp + q2 * 8;
                size_t obase = ((size_t)(bb2 * CCH + dd) * T2 + tb) * NN;
#pragma unroll
                for (int nf = 0; nf < 4; nf++) {
                    int m = m0 + mw * 32 + nf * 8 + thr * 2;
                    if (m < NN)     out[obase + m]     = omax[mf][nf][q2 * 2];
                    if (m + 1 < NN) out[obase + m + 1] = omax[mf][nf][q2 * 2 + 1];
                }
            }
        }
    }
}

// ---------------------------------------------------------------------------
extern "C" void kernel_launch(void* const* d_in, const int* in_sizes, int n_in,
                              void* d_out, int out_size) {
    const float* x    = (const float*)d_in[0];
    const float* te   = (const float*)d_in[1];
    const float* se   = (const float*)d_in[2];
    const float* adj  = (const float*)d_in[3];
    const float* Wp   = (const float*)d_in[4];
    const float* bias = (const float*)d_in[5];
    float* out = (float*)d_out;

    cudaFuncSetAttribute(stsgcl_mma_kernel,
                         cudaFuncAttributeMaxDynamicSharedMemorySize, DSMEM_BYTES);

    prep_fused<<<PH_BLOCKS + PB_BLOCKS, 256>>>(x, te, se, adj);

    dim3 grid(NP / 128, 80);   // (7, 80): m-tiles x bt-quads
    stsgcl_mma_kernel<<<grid, NTHREADS, DSMEM_BYTES>>>(Wp, bias, out);
}